// round 1
// baseline (speedup 1.0000x reference)
#include <cuda_runtime.h>

// DynamicFilterLayer2D: out[b,c,h,w] = sum_{i,j in 3x3} xpad[b,c,h+i,w+j] * f[b,c,i*3+j,h,w]
// Shapes fixed: B=8, C=32, H=256, W=256, K=3 (zero padding of 1).
// HBM-bound: ~740 MB mandatory traffic. Strategy: float4 along W (aligned since W%4==0),
// filters read once coalesced, x reuse via L1/L2.

static constexpr int B = 8;
static constexpr int C = 32;
static constexpr int H = 256;
static constexpr int W = 256;
static constexpr int HW = H * W;
static constexpr int W4 = W / 4;

__global__ __launch_bounds__(256)
void dynamic_filter_kernel(const float* __restrict__ x,
                           const float* __restrict__ f,
                           float* __restrict__ out)
{
    int tid = blockIdx.x * blockDim.x + threadIdx.x;
    // total threads = B*C*H*W4 = 4,194,304
    int w4 = tid & (W4 - 1);
    int t = tid >> 6;          // W4 = 64
    int h = t & (H - 1);
    int bc = t >> 8;           // H = 256
    if (bc >= B * C) return;

    const int w0 = w4 * 4;
    const long xbase = (long)bc * HW;
    const long fbase = (long)bc * 9 * HW;

    float4 acc = make_float4(0.f, 0.f, 0.f, 0.f);

    #pragma unroll
    for (int i = 0; i < 3; i++) {
        const int hr = h + i - 1;
        if (hr < 0 || hr >= H) continue;

        const float* xrow = x + xbase + (long)hr * W;
        const float4 cen = *reinterpret_cast<const float4*>(xrow + w0);
        const float xl = (w0 > 0)       ? __ldg(xrow + w0 - 1) : 0.f;
        const float xr = (w0 + 4 < W)   ? __ldg(xrow + w0 + 4) : 0.f;

        // v[0..5] = x at columns w0-1 .. w0+4 (register array, constant-indexed)
        const float v0 = xl, v1 = cen.x, v2 = cen.y, v3 = cen.z, v4 = cen.w, v5 = xr;

        const float* fp = f + fbase + (long)(i * 3) * HW + (long)h * W + w0;
        {
            const float4 fv = *reinterpret_cast<const float4*>(fp);            // j = 0
            acc.x = fmaf(fv.x, v0, acc.x);
            acc.y = fmaf(fv.y, v1, acc.y);
            acc.z = fmaf(fv.z, v2, acc.z);
            acc.w = fmaf(fv.w, v3, acc.w);
        }
        {
            const float4 fv = *reinterpret_cast<const float4*>(fp + HW);       // j = 1
            acc.x = fmaf(fv.x, v1, acc.x);
            acc.y = fmaf(fv.y, v2, acc.y);
            acc.z = fmaf(fv.z, v3, acc.z);
            acc.w = fmaf(fv.w, v4, acc.w);
        }
        {
            const float4 fv = *reinterpret_cast<const float4*>(fp + 2 * HW);   // j = 2
            acc.x = fmaf(fv.x, v2, acc.x);
            acc.y = fmaf(fv.y, v3, acc.y);
            acc.z = fmaf(fv.z, v4, acc.z);
            acc.w = fmaf(fv.w, v5, acc.w);
        }
    }

    *reinterpret_cast<float4*>(out + xbase + (long)h * W + w0) = acc;
}

extern "C" void kernel_launch(void* const* d_in, const int* in_sizes, int n_in,
                              void* d_out, int out_size)
{
    const float* x = (const float*)d_in[0];
    const float* f = (const float*)d_in[1];
    float* out = (float*)d_out;

    const int total = B * C * H * W4;       // 4,194,304 threads
    const int threads = 256;
    const int blocks = total / threads;     // 16384
    dynamic_filter_kernel<<<blocks, threads>>>(x, f, out);
}